// round 1
// baseline (speedup 1.0000x reference)
#include <cuda_runtime.h>
#include <math.h>

#define NN 50000
#define EE 800000
#define FF 128
#define HH 8
#define CC 16
#define NLAY 5
#define GNFREQ 3
#define ETOT (EE + NN)

// ---------------- device scratch (no allocations allowed) ----------------
__device__ float g_x[NN * FF];
__device__ float g_h[NN * FF];
__device__ float g_as[NN * HH];
__device__ float g_ad[NN * HH];
__device__ float g_sagg[NN];
__device__ float g_dinv[NN];
__device__ int   g_rowptr[NN + 1];
__device__ int   g_deg[NN];
__device__ int   g_cursor[NN];
__device__ int   g_col[ETOT];
__device__ float g_mu[FF];
__device__ float g_var[FF];

// ---------------- CSR construction ----------------
__global__ void k_init_deg(int n) {
    int i = blockIdx.x * blockDim.x + threadIdx.x;
    if (i < n) g_deg[i] = 1;  // self loop
}

__global__ void k_deg_edges(const int* __restrict__ dst, int e) {
    int i = blockIdx.x * blockDim.x + threadIdx.x;
    if (i < e) atomicAdd(&g_deg[dst[i]], 1);
}

// single-block exclusive scan of g_deg -> g_rowptr (n up to ~50k, fine)
__global__ void k_scan(int n) {
    __shared__ int buf[1024];
    __shared__ int carry;
    if (threadIdx.x == 0) carry = 0;
    __syncthreads();
    for (int base = 0; base < n; base += 1024) {
        int i = base + threadIdx.x;
        int v = (i < n) ? g_deg[i] : 0;
        buf[threadIdx.x] = v;
        __syncthreads();
        for (int off = 1; off < 1024; off <<= 1) {
            int t = (threadIdx.x >= off) ? buf[threadIdx.x - off] : 0;
            __syncthreads();
            buf[threadIdx.x] += t;
            __syncthreads();
        }
        if (i < n) g_rowptr[i] = carry + buf[threadIdx.x] - v;
        __syncthreads();
        if (threadIdx.x == 0) carry += buf[1023];
        __syncthreads();
    }
    if (threadIdx.x == 0) g_rowptr[n] = carry;
}

__global__ void k_selfloop(int n) {
    int i = blockIdx.x * blockDim.x + threadIdx.x;
    if (i < n) {
        int p = g_rowptr[i];
        g_col[p] = i;
        g_cursor[i] = p + 1;
    }
}

__global__ void k_fill(const int* __restrict__ src, const int* __restrict__ dst, int e) {
    int i = blockIdx.x * blockDim.x + threadIdx.x;
    if (i < e) {
        int p = atomicAdd(&g_cursor[dst[i]], 1);
        g_col[p] = src[i];
    }
}

// ---------------- GCN (rank-1 collapse) ----------------
__global__ void k_dinv(int n) {
    int i = blockIdx.x * blockDim.x + threadIdx.x;
    if (i < n) g_dinv[i] = rsqrtf((float)(g_rowptr[i + 1] - g_rowptr[i]));
}

__global__ void k_gcn_agg(const float* __restrict__ sig, int n) {
    int i = blockIdx.x * blockDim.x + threadIdx.x;
    if (i >= n) return;
    int beg = g_rowptr[i], end = g_rowptr[i + 1];
    float s = 0.f;
    for (int j = beg; j < end; j++) {
        int u = g_col[j];
        s += g_dinv[u] * sig[u];
    }
    g_sagg[i] = s * g_dinv[i];
}

__global__ void k_gcn_x(const float* __restrict__ w, const float* __restrict__ b, int n) {
    int idx = blockIdx.x * blockDim.x + threadIdx.x;
    if (idx >= n * FF) return;
    int node = idx >> 7, f = idx & (FF - 1);
    float v = g_sagg[node] * w[f] + b[f];
    g_x[idx] = v > 0.f ? v : 0.f;
}

// ---------------- GraphNorm ----------------
__global__ void k_zero_mv() {
    int t = threadIdx.x;
    if (t < FF) { g_mu[t] = 0.f; g_var[t] = 0.f; }
}

__global__ void k_colsum(int n) {
    int f = threadIdx.x;
    int base = blockIdx.x * 128;
    float s = 0.f;
#pragma unroll 4
    for (int r = 0; r < 128; r++) {
        int nd = base + r;
        if (nd < n) s += g_x[nd * FF + f];
    }
    atomicAdd(&g_mu[f], s);
}

__global__ void k_colvar(const float* __restrict__ scale, int n) {
    int f = threadIdx.x;
    int base = blockIdx.x * 128;
    float mum = g_mu[f] * (1.0f / (float)n) * scale[f];
    float s = 0.f;
#pragma unroll 4
    for (int r = 0; r < 128; r++) {
        int nd = base + r;
        if (nd < n) {
            float v = g_x[nd * FF + f] - mum;
            s += v * v;
        }
    }
    atomicAdd(&g_var[f], s);
}

__global__ void k_gnapply(const float* __restrict__ w, const float* __restrict__ b,
                          const float* __restrict__ scale, int n) {
    int idx = blockIdx.x * blockDim.x + threadIdx.x;
    if (idx >= n * FF) return;
    int f = idx & (FF - 1);
    float invn = 1.0f / (float)n;
    float mum = g_mu[f] * invn * scale[f];
    float inv = rsqrtf(g_var[f] * invn + 1e-5f);
    g_x[idx] = w[f] * (g_x[idx] - mum) * inv + b[f];
}

// ---------------- dense GEMM: h = x @ W (W is 128x128, row-major) ----------------
// block: 256 threads = 8 warps; each warp computes 4 nodes x 128 features.
// W staged in shared (64KB) + 32-node x tile (16KB) -> 80KB dynamic shared.
__global__ void k_gemm(const float* __restrict__ W, int n) {
    extern __shared__ float smem[];
    float* Ws = smem;                 // 128*128
    float* Xs = smem + FF * FF;       // 32*128
    int tid = threadIdx.x;

    const float4* W4 = (const float4*)W;
    float4* Ws4 = (float4*)Ws;
    for (int i = tid; i < FF * FF / 4; i += blockDim.x) Ws4[i] = W4[i];

    int nb = blockIdx.x * 32;
    float4* Xs4 = (float4*)Xs;
    for (int i = tid; i < 32 * FF / 4; i += blockDim.x) {
        int r = i / (FF / 4), cq = i % (FF / 4);
        int nd = nb + r;
        Xs4[i] = (nd < n) ? ((const float4*)(g_x + (size_t)nd * FF))[cq]
                          : make_float4(0.f, 0.f, 0.f, 0.f);
    }
    __syncthreads();

    int warp = tid >> 5, lane = tid & 31;
    int m0 = warp * 4;
    float4 a0 = {0, 0, 0, 0}, a1 = a0, a2 = a0, a3 = a0;

#pragma unroll 4
    for (int k = 0; k < FF; k++) {
        float4 w4 = ((float4*)(Ws + k * FF))[lane];
        float x0 = Xs[(m0 + 0) * FF + k];
        float x1 = Xs[(m0 + 1) * FF + k];
        float x2 = Xs[(m0 + 2) * FF + k];
        float x3 = Xs[(m0 + 3) * FF + k];
        a0.x += x0 * w4.x; a0.y += x0 * w4.y; a0.z += x0 * w4.z; a0.w += x0 * w4.w;
        a1.x += x1 * w4.x; a1.y += x1 * w4.y; a1.z += x1 * w4.z; a1.w += x1 * w4.w;
        a2.x += x2 * w4.x; a2.y += x2 * w4.y; a2.z += x2 * w4.z; a2.w += x2 * w4.w;
        a3.x += x3 * w4.x; a3.y += x3 * w4.y; a3.z += x3 * w4.z; a3.w += x3 * w4.w;
    }

    int nd;
    nd = nb + m0 + 0; if (nd < n) ((float4*)(g_h + (size_t)nd * FF))[lane] = a0;
    nd = nb + m0 + 1; if (nd < n) ((float4*)(g_h + (size_t)nd * FF))[lane] = a1;
    nd = nb + m0 + 2; if (nd < n) ((float4*)(g_h + (size_t)nd * FF))[lane] = a2;
    nd = nb + m0 + 3; if (nd < n) ((float4*)(g_h + (size_t)nd * FF))[lane] = a3;
}

// ---------------- attention coefficients ----------------
__global__ void k_attcoef(const float* __restrict__ atts, const float* __restrict__ attd, int n) {
    int idx = blockIdx.x * blockDim.x + threadIdx.x;
    if (idx >= n * HH) return;
    int node = idx >> 3, hd = idx & 7;
    const float* hp = g_h + (size_t)node * FF + hd * CC;
    float s = 0.f, d = 0.f;
#pragma unroll
    for (int c = 0; c < CC; c++) {
        float v = hp[c];
        s += v * atts[hd * CC + c];
        d += v * attd[hd * CC + c];
    }
    g_as[idx] = s;
    g_ad[idx] = d;
}

// ---------------- edge softmax + aggregation + residual (warp per node) ----------------
__global__ void k_attn(const float* __restrict__ gb, int n) {
    int gw = (blockIdx.x * blockDim.x + threadIdx.x) >> 5;
    int lane = threadIdx.x & 31;
    if (gw >= n) return;
    int node = gw;
    int beg = g_rowptr[node], end = g_rowptr[node + 1];
    int hd = lane >> 2, sub = lane & 3;
    float adh = g_ad[node * HH + hd];

    // online softmax (max + sum), lanes within a head-group of 4 split edges
    float m = -1e30f, s = 0.f;
    for (int j = beg + sub; j < end; j += 4) {
        int u = g_col[j];
        float ev = g_as[u * HH + hd] + adh;
        ev = ev > 0.f ? ev : 0.2f * ev;
        float M = fmaxf(m, ev);
        s = s * __expf(m - M) + __expf(ev - M);
        m = M;
    }
#pragma unroll
    for (int off = 1; off < 4; off <<= 1) {
        float om = __shfl_xor_sync(0xffffffffu, m, off);
        float os = __shfl_xor_sync(0xffffffffu, s, off);
        float M = fmaxf(m, om);
        s = s * __expf(m - M) + os * __expf(om - M);
        m = M;
    }
    float rd = 1.0f / s;

    // accumulate: lane owns features [lane*4, lane*4+3] (all within head lane/4)
    float4 acc = {0.f, 0.f, 0.f, 0.f};
    for (int j = beg; j < end; j++) {
        int u = g_col[j];
        float ev = g_as[u * HH + hd] + adh;
        ev = ev > 0.f ? ev : 0.2f * ev;
        float alpha = __expf(ev - m) * rd;
        float4 hv = ((const float4*)(g_h + (size_t)u * FF))[lane];
        acc.x += alpha * hv.x;
        acc.y += alpha * hv.y;
        acc.z += alpha * hv.z;
        acc.w += alpha * hv.w;
    }

    float4 b4 = ((const float4*)gb)[lane];
    float4 xv = ((float4*)(g_x + (size_t)node * FF))[lane];
    xv.x += fmaxf(acc.x + b4.x, 0.f);
    xv.y += fmaxf(acc.y + b4.y, 0.f);
    xv.z += fmaxf(acc.z + b4.z, 0.f);
    xv.w += fmaxf(acc.w + b4.w, 0.f);
    ((float4*)(g_x + (size_t)node * FF))[lane] = xv;
}

// ---------------- final linear: out = x @ lin_w (128x64) + lin_b ----------------
__global__ void k_linear(const float* __restrict__ W, const float* __restrict__ b,
                         float* __restrict__ out, int n) {
    int idx = blockIdx.x * blockDim.x + threadIdx.x;
    if (idx >= n * 64) return;
    int node = idx >> 6, fo = idx & 63;
    const float* xr = g_x + (size_t)node * FF;
    float s = b[fo];
#pragma unroll 8
    for (int k = 0; k < FF; k++) s += xr[k] * W[k * 64 + fo];
    out[idx] = s;
}

// ---------------- launch ----------------
extern "C" void kernel_launch(void* const* d_in, const int* in_sizes, int n_in,
                              void* d_out, int out_size) {
    const float* signals = (const float*)d_in[0];
    const int*   ei      = (const int*)d_in[1];
    const float* gcn_w   = (const float*)d_in[2];
    const float* gcn_b   = (const float*)d_in[3];
    const float* gat_w   = (const float*)d_in[4];
    const float* att_src = (const float*)d_in[5];
    const float* att_dst = (const float*)d_in[6];
    const float* gat_b   = (const float*)d_in[7];
    const float* gn_w    = (const float*)d_in[8];
    const float* gn_b    = (const float*)d_in[9];
    const float* gn_s    = (const float*)d_in[10];
    const float* lin_w   = (const float*)d_in[11];
    const float* lin_b   = (const float*)d_in[12];

    int n = in_sizes[0];
    int e = in_sizes[1] / 2;
    const int* src = ei;
    const int* dst = ei + e;

    cudaFuncSetAttribute(k_gemm, cudaFuncAttributeMaxDynamicSharedMemorySize, 81920);

    const int B = 256;
    // CSR build (dst-sorted adjacency with self loops)
    k_init_deg<<<(n + B - 1) / B, B>>>(n);
    k_deg_edges<<<(e + B - 1) / B, B>>>(dst, e);
    k_scan<<<1, 1024>>>(n);
    k_selfloop<<<(n + B - 1) / B, B>>>(n);
    k_fill<<<(e + B - 1) / B, B>>>(src, dst, e);
    k_dinv<<<(n + B - 1) / B, B>>>(n);

    // GCN (rank-1 collapsed)
    k_gcn_agg<<<(n + B - 1) / B, B>>>(signals, n);
    k_gcn_x<<<(n * FF + B - 1) / B, B>>>(gcn_w, gcn_b, n);

    // GAT layers
    for (int i = 0; i < NLAY; i++) {
        if (i % GNFREQ == 0) {
            int g = i / GNFREQ;
            k_zero_mv<<<1, 128>>>();
            k_colsum<<<(n + 127) / 128, 128>>>(n);
            k_colvar<<<(n + 127) / 128, 128>>>(gn_s + g * FF, n);
            k_gnapply<<<(n * FF + B - 1) / B, B>>>(gn_w + g * FF, gn_b + g * FF, gn_s + g * FF, n);
        }
        k_gemm<<<(n + 31) / 32, 256, 81920>>>(gat_w + (size_t)i * FF * FF, n);
        k_attcoef<<<(n * HH + B - 1) / B, B>>>(att_src + i * HH * CC, att_dst + i * HH * CC, n);
        k_attn<<<(n * 32 + B - 1) / B, B>>>(gat_b + i * FF, n);
    }

    // output projection
    k_linear<<<(n * 64 + B - 1) / B, B>>>(lin_w, lin_b, (float*)d_out, n);
}

// round 2
// speedup vs baseline: 1.3374x; 1.3374x over previous
#include <cuda_runtime.h>
#include <math.h>

#define NN 50000
#define EE 800000
#define FF 128
#define HH 8
#define CC 16
#define NLAY 5
#define GNFREQ 3
#define ETOT (EE + NN)

// ---------------- device scratch ----------------
__device__ float g_x[NN * FF];
__device__ float g_h[NN * FF];
__device__ float g_as[NN * HH];
__device__ float g_ad[NN * HH];
__device__ float g_sagg[NN];
__device__ float g_dinv[NN];
__device__ int   g_rowptr[NN + 1];
__device__ int   g_deg[NN];
__device__ int   g_cursor[NN];
__device__ int   g_col[ETOT];
__device__ float g_s1[2 * FF];   // per-GN-group feature sums
__device__ float g_s2[2 * FF];   // per-GN-group feature sum-of-squares

// ---------------- zero scratch ----------------
__global__ void k_zero(int n) {
    int i = blockIdx.x * blockDim.x + threadIdx.x;
    if (i < n) g_deg[i] = 0;
    if (i < 2 * FF) { g_s1[i] = 0.f; g_s2[i] = 0.f; }
}

__global__ void k_deg_edges(const int* __restrict__ dst, int e) {
    int i = blockIdx.x * blockDim.x + threadIdx.x;
    if (i < e) atomicAdd(&g_deg[dst[i]], 1);
}

// fast single-block scan: 1024 threads x 16 elems, warp-shuffle hierarchy.
// adds +1 per node for the self loop while loading.
__global__ void k_scan(int n) {
    __shared__ int warp_sums[32];
    __shared__ int s_carry;
    const int VT = 16;
    int tid = threadIdx.x, lane = tid & 31, warp = tid >> 5;
    if (tid == 0) s_carry = 0;
    __syncthreads();
    const int TILE = 1024 * VT;
    for (int base = 0; base < n; base += TILE) {
        int idx0 = base + tid * VT;
        int v[VT];
        int tsum = 0;
#pragma unroll
        for (int j = 0; j < VT; j++) {
            int i = idx0 + j;
            v[j] = (i < n) ? (g_deg[i] + 1) : 0;
            tsum += v[j];
        }
        int x = tsum;
#pragma unroll
        for (int o = 1; o < 32; o <<= 1) {
            int t = __shfl_up_sync(0xffffffffu, x, o);
            if (lane >= o) x += t;
        }
        if (lane == 31) warp_sums[warp] = x;
        __syncthreads();
        if (warp == 0) {
            int y = warp_sums[lane];
#pragma unroll
            for (int o = 1; o < 32; o <<= 1) {
                int t = __shfl_up_sync(0xffffffffu, y, o);
                if (lane >= o) y += t;
            }
            warp_sums[lane] = y;
        }
        __syncthreads();
        int warp_excl = (warp == 0) ? 0 : warp_sums[warp - 1];
        int run = s_carry + warp_excl + (x - tsum);
#pragma unroll
        for (int j = 0; j < VT; j++) {
            int i = idx0 + j;
            if (i < n) g_rowptr[i] = run;
            run += v[j];
        }
        __syncthreads();
        if (tid == 0) s_carry += warp_sums[31];
        __syncthreads();
    }
    if (tid == 0) g_rowptr[n] = s_carry;
}

__global__ void k_selfloop(int n) {
    int i = blockIdx.x * blockDim.x + threadIdx.x;
    if (i < n) {
        int p = g_rowptr[i];
        g_col[p] = i;
        g_cursor[i] = p + 1;
        g_dinv[i] = rsqrtf((float)(g_rowptr[i + 1] - p));
    }
}

__global__ void k_fill(const int* __restrict__ src, const int* __restrict__ dst, int e) {
    int i = blockIdx.x * blockDim.x + threadIdx.x;
    if (i < e) {
        int p = atomicAdd(&g_cursor[dst[i]], 1);
        g_col[p] = src[i];
    }
}

// ---------------- GCN (rank-1 collapse) ----------------
__global__ void k_gcn_agg(const float* __restrict__ sig, int n) {
    int i = blockIdx.x * blockDim.x + threadIdx.x;
    if (i >= n) return;
    int beg = g_rowptr[i], end = g_rowptr[i + 1];
    float s = 0.f;
    for (int j = beg; j < end; j++) {
        int u = g_col[j];
        s += g_dinv[u] * sig[u];
    }
    g_sagg[i] = s * g_dinv[i];
}

// GCN feature build + GraphNorm-group-0 stats in one pass.
// block: 128 threads (thread = feature), 64 nodes per block.
__global__ void k_gcn_x(const float* __restrict__ w, const float* __restrict__ b, int n) {
    int f = threadIdx.x;
    float wf = w[f], bf = b[f];
    int base = blockIdx.x * 64;
    float s1 = 0.f, s2 = 0.f;
    for (int r = 0; r < 64; r++) {
        int nd = base + r;
        if (nd >= n) break;
        float v = fmaxf(fmaf(g_sagg[nd], wf, bf), 0.f);
        g_x[nd * FF + f] = v;
        s1 += v;
        s2 += v * v;
    }
    atomicAdd(&g_s1[f], s1);
    atomicAdd(&g_s2[f], s2);
}

// ---------------- GraphNorm apply (from sum / sumsq) ----------------
__global__ void k_gnapply(const float* __restrict__ w, const float* __restrict__ b,
                          const float* __restrict__ scale, int grp, int n) {
    int idx = blockIdx.x * blockDim.x + threadIdx.x;   // over n*32 float4
    if (idx >= n * (FF / 4)) return;
    int f4 = idx & 31;
    float4 wv = ((const float4*)w)[f4];
    float4 bv = ((const float4*)b)[f4];
    float4 sv = ((const float4*)scale)[f4];
    float4 s1 = ((const float4*)(g_s1 + grp * FF))[f4];
    float4 s2 = ((const float4*)(g_s2 + grp * FF))[f4];
    float invn = 1.0f / (float)n;
    float4 xv = ((float4*)g_x)[idx];
#define GN1(c)                                                             \
    {                                                                      \
        float mu = s1.c * invn, m2 = s2.c * invn;                          \
        float mum = sv.c * mu;                                             \
        float var = m2 - 2.f * mum * mu + mum * mum;                       \
        float inv = rsqrtf(var + 1e-5f);                                   \
        xv.c = wv.c * (xv.c - mum) * inv + bv.c;                           \
    }
    GN1(x) GN1(y) GN1(z) GN1(w)
#undef GN1
    ((float4*)g_x)[idx] = xv;
}

// ---------------- dense GEMM h = x @ W + fused attention coefficients ----------
// 256 threads = 8 warps; warp computes 4 nodes x 128 feats (lane owns feats 4l..4l+3).
__global__ void k_gemm(const float* __restrict__ W,
                       const float* __restrict__ atts, const float* __restrict__ attd,
                       int n) {
    extern __shared__ float smem[];
    float* Ws = smem;            // 128*128
    float* Xs = smem + FF * FF;  // 32*128
    int tid = threadIdx.x;

    const float4* W4 = (const float4*)W;
    float4* Ws4 = (float4*)Ws;
    for (int i = tid; i < FF * FF / 4; i += blockDim.x) Ws4[i] = W4[i];

    int nb = blockIdx.x * 32;
    float4* Xs4 = (float4*)Xs;
    for (int i = tid; i < 32 * FF / 4; i += blockDim.x) {
        int r = i / (FF / 4), cq = i % (FF / 4);
        int nd = nb + r;
        Xs4[i] = (nd < n) ? ((const float4*)(g_x + (size_t)nd * FF))[cq]
                          : make_float4(0.f, 0.f, 0.f, 0.f);
    }
    __syncthreads();

    int warp = tid >> 5, lane = tid & 31;
    int m0 = warp * 4;
    float4 a0 = {0, 0, 0, 0}, a1 = a0, a2 = a0, a3 = a0;

    const float4* X0 = (const float4*)(Xs + (m0 + 0) * FF);
    const float4* X1 = (const float4*)(Xs + (m0 + 1) * FF);
    const float4* X2 = (const float4*)(Xs + (m0 + 2) * FF);
    const float4* X3 = (const float4*)(Xs + (m0 + 3) * FF);

#pragma unroll
    for (int kq = 0; kq < FF / 4; kq++) {
        float4 x0 = X0[kq], x1 = X1[kq], x2 = X2[kq], x3 = X3[kq];
#pragma unroll
        for (int kk = 0; kk < 4; kk++) {
            float4 w4 = Ws4[(kq * 4 + kk) * 32 + lane];
            float v0 = (&x0.x)[kk], v1 = (&x1.x)[kk], v2 = (&x2.x)[kk], v3 = (&x3.x)[kk];
            a0.x += v0 * w4.x; a0.y += v0 * w4.y; a0.z += v0 * w4.z; a0.w += v0 * w4.w;
            a1.x += v1 * w4.x; a1.y += v1 * w4.y; a1.z += v1 * w4.z; a1.w += v1 * w4.w;
            a2.x += v2 * w4.x; a2.y += v2 * w4.y; a2.z += v2 * w4.z; a2.w += v2 * w4.w;
            a3.x += v3 * w4.x; a3.y += v3 * w4.y; a3.z += v3 * w4.z; a3.w += v3 * w4.w;
        }
    }

    // store h
    int nd;
    nd = nb + m0 + 0; if (nd < n) ((float4*)(g_h + (size_t)nd * FF))[lane] = a0;
    nd = nb + m0 + 1; if (nd < n) ((float4*)(g_h + (size_t)nd * FF))[lane] = a1;
    nd = nb + m0 + 2; if (nd < n) ((float4*)(g_h + (size_t)nd * FF))[lane] = a2;
    nd = nb + m0 + 3; if (nd < n) ((float4*)(g_h + (size_t)nd * FF))[lane] = a3;

    // fused attention coefficients: a_s/a_d per (node, head)
    float4 as4 = ((const float4*)atts)[lane];
    float4 ad4 = ((const float4*)attd)[lane];
    int hd = lane >> 2;
#define COEF(acc, R)                                                              \
    {                                                                             \
        float sv = acc.x * as4.x + acc.y * as4.y + acc.z * as4.z + acc.w * as4.w; \
        float dv = acc.x * ad4.x + acc.y * ad4.y + acc.z * ad4.z + acc.w * ad4.w; \
        sv += __shfl_xor_sync(0xffffffffu, sv, 1);                                \
        dv += __shfl_xor_sync(0xffffffffu, dv, 1);                                \
        sv += __shfl_xor_sync(0xffffffffu, sv, 2);                                \
        dv += __shfl_xor_sync(0xffffffffu, dv, 2);                                \
        int nd2 = nb + m0 + R;                                                    \
        if ((lane & 3) == 0 && nd2 < n) {                                         \
            g_as[nd2 * HH + hd] = sv;                                             \
            g_ad[nd2 * HH + hd] = dv;                                             \
        }                                                                         \
    }
    COEF(a0, 0) COEF(a1, 1) COEF(a2, 2) COEF(a3, 3)
#undef COEF
}

// ---------------- edge softmax + aggregation + residual (warp per node) -------
// One-pass: exp without max subtraction (attention logits are O(0.1) here).
// STATS: also accumulate GraphNorm-group-1 sums from the updated x.
template <int STATS>
__global__ void k_attn(const float* __restrict__ gb, int n) {
    __shared__ float bsum[FF];
    __shared__ float bsq[FF];
    int tid = threadIdx.x;
    int warp = tid >> 5, lane = tid & 31;
    int node = blockIdx.x * 8 + warp;

    if (STATS) {
        if (tid < FF) { bsum[tid] = 0.f; bsq[tid] = 0.f; }
        __syncthreads();
    }

    float4 xv = {0, 0, 0, 0};
    if (node < n) {
        int beg = g_rowptr[node], end = g_rowptr[node + 1];
        int hd = lane >> 2;
        float adh = g_ad[node * HH + hd];

        float s = 0.f;
        float4 acc = {0.f, 0.f, 0.f, 0.f};
        int j = beg;
        for (; j + 1 < end; j += 2) {
            int u0 = g_col[j], u1 = g_col[j + 1];
            float e0 = g_as[u0 * HH + hd] + adh;
            float e1 = g_as[u1 * HH + hd] + adh;
            e0 = e0 > 0.f ? e0 : 0.2f * e0;
            e1 = e1 > 0.f ? e1 : 0.2f * e1;
            float w0 = __expf(e0), w1 = __expf(e1);
            float4 h0 = ((const float4*)(g_h + (size_t)u0 * FF))[lane];
            float4 h1 = ((const float4*)(g_h + (size_t)u1 * FF))[lane];
            s += w0 + w1;
            acc.x += w0 * h0.x + w1 * h1.x;
            acc.y += w0 * h0.y + w1 * h1.y;
            acc.z += w0 * h0.z + w1 * h1.z;
            acc.w += w0 * h0.w + w1 * h1.w;
        }
        if (j < end) {
            int u0 = g_col[j];
            float e0 = g_as[u0 * HH + hd] + adh;
            e0 = e0 > 0.f ? e0 : 0.2f * e0;
            float w0 = __expf(e0);
            float4 h0 = ((const float4*)(g_h + (size_t)u0 * FF))[lane];
            s += w0;
            acc.x += w0 * h0.x;
            acc.y += w0 * h0.y;
            acc.z += w0 * h0.z;
            acc.w += w0 * h0.w;
        }
        float rd = 1.0f / s;

        float4 b4 = ((const float4*)gb)[lane];
        xv = ((float4*)(g_x + (size_t)node * FF))[lane];
        xv.x += fmaxf(acc.x * rd + b4.x, 0.f);
        xv.y += fmaxf(acc.y * rd + b4.y, 0.f);
        xv.z += fmaxf(acc.z * rd + b4.z, 0.f);
        xv.w += fmaxf(acc.w * rd + b4.w, 0.f);
        ((float4*)(g_x + (size_t)node * FF))[lane] = xv;
    }

    if (STATS) {
        if (node < n) {
            int f0 = lane * 4;
            atomicAdd(&bsum[f0 + 0], xv.x); atomicAdd(&bsq[f0 + 0], xv.x * xv.x);
            atomicAdd(&bsum[f0 + 1], xv.y); atomicAdd(&bsq[f0 + 1], xv.y * xv.y);
            atomicAdd(&bsum[f0 + 2], xv.z); atomicAdd(&bsq[f0 + 2], xv.z * xv.z);
            atomicAdd(&bsum[f0 + 3], xv.w); atomicAdd(&bsq[f0 + 3], xv.w * xv.w);
        }
        __syncthreads();
        if (tid < FF) {
            atomicAdd(&g_s1[FF + tid], bsum[tid]);
            atomicAdd(&g_s2[FF + tid], bsq[tid]);
        }
    }
}

// ---------------- final linear: out = x @ lin_w (128x64) + lin_b ----------------
__global__ void k_linear(const float* __restrict__ W, const float* __restrict__ b,
                         float* __restrict__ out, int n) {
    int idx = blockIdx.x * blockDim.x + threadIdx.x;
    if (idx >= n * 64) return;
    int node = idx >> 6, fo = idx & 63;
    const float4* xr = (const float4*)(g_x + (size_t)node * FF);
    float s = b[fo];
#pragma unroll
    for (int kq = 0; kq < FF / 4; kq++) {
        float4 xk = xr[kq];
        s += xk.x * W[(kq * 4 + 0) * 64 + fo];
        s += xk.y * W[(kq * 4 + 1) * 64 + fo];
        s += xk.z * W[(kq * 4 + 2) * 64 + fo];
        s += xk.w * W[(kq * 4 + 3) * 64 + fo];
    }
    out[idx] = s;
}

// ---------------- launch ----------------
extern "C" void kernel_launch(void* const* d_in, const int* in_sizes, int n_in,
                              void* d_out, int out_size) {
    const float* signals = (const float*)d_in[0];
    const int*   ei      = (const int*)d_in[1];
    const float* gcn_w   = (const float*)d_in[2];
    const float* gcn_b   = (const float*)d_in[3];
    const float* gat_w   = (const float*)d_in[4];
    const float* att_src = (const float*)d_in[5];
    const float* att_dst = (const float*)d_in[6];
    const float* gat_b   = (const float*)d_in[7];
    const float* gn_w    = (const float*)d_in[8];
    const float* gn_b    = (const float*)d_in[9];
    const float* gn_s    = (const float*)d_in[10];
    const float* lin_w   = (const float*)d_in[11];
    const float* lin_b   = (const float*)d_in[12];

    int n = in_sizes[0];
    int e = in_sizes[1] / 2;
    const int* src = ei;
    const int* dst = ei + e;

    cudaFuncSetAttribute(k_gemm, cudaFuncAttributeMaxDynamicSharedMemorySize, 81920);

    const int B = 256;
    k_zero<<<(n + B - 1) / B, B>>>(n);
    k_deg_edges<<<(e + B - 1) / B, B>>>(dst, e);
    k_scan<<<1, 1024>>>(n);
    k_selfloop<<<(n + B - 1) / B, B>>>(n);
    k_fill<<<(e + B - 1) / B, B>>>(src, dst, e);

    k_gcn_agg<<<(n + B - 1) / B, B>>>(signals, n);
    k_gcn_x<<<(n + 63) / 64, 128>>>(gcn_w, gcn_b, n);   // + GN group-0 stats

    for (int i = 0; i < NLAY; i++) {
        if (i % GNFREQ == 0) {
            int g = i / GNFREQ;
            k_gnapply<<<(n * 32 + B - 1) / B, B>>>(gn_w + g * FF, gn_b + g * FF,
                                                   gn_s + g * FF, g, n);
        }
        k_gemm<<<(n + 31) / 32, 256, 81920>>>(gat_w + (size_t)i * FF * FF,
                                              att_src + i * HH * CC,
                                              att_dst + i * HH * CC, n);
        if (i == 2) {
            k_attn<1><<<(n + 7) / 8, 256>>>(gat_b + i * FF, n);  // + GN group-1 stats
        } else {
            k_attn<0><<<(n + 7) / 8, 256>>>(gat_b + i * FF, n);
        }
    }

    k_linear<<<(n * 64 + B - 1) / B, B>>>(lin_w, lin_b, (float*)d_out, n);
}

// round 4
// speedup vs baseline: 2.0956x; 1.5668x over previous
#include <cuda_runtime.h>
#include <cuda_fp16.h>
#include <cstdint>
#include <cstddef>
#include <math.h>

#define NN 50000
#define EE 800000
#define FF 128
#define HH 8
#define CC 16
#define NLAY 5
#define GNFREQ 3
#define ETOT (EE + NN)

// Xs row pitch in halves (272 B): 68 words %32 = 4 banks/row -> conflict-free ldmatrix
#define XP 136

// ---------------- device scratch ----------------
__device__ float  g_x[NN * FF];
__device__ __half g_hh[NN * FF];
__device__ float  g_as[NN * HH];
__device__ float  g_ad[NN * HH];
__device__ float  g_sagg[NN];
__device__ float  g_dinv[NN];
__device__ int    g_rowptr[NN + 1];
__device__ int    g_deg[NN];
__device__ int    g_cursor[NN];
__device__ int    g_col[ETOT];
__device__ float  g_s1[2 * FF];
__device__ float  g_s2[2 * FF];

// ---------------- CSR build ----------------
__global__ void k_zero(int n) {
    int i = blockIdx.x * blockDim.x + threadIdx.x;
    if (i < n) g_deg[i] = 0;
    if (i < 2 * FF) { g_s1[i] = 0.f; g_s2[i] = 0.f; }
}

__global__ void k_deg_edges(const int* __restrict__ dst, int e) {
    int i = blockIdx.x * blockDim.x + threadIdx.x;
    if (i < e) atomicAdd(&g_deg[dst[i]], 1);
}

__global__ void k_scan(int n) {
    __shared__ int warp_sums[32];
    __shared__ int s_carry;
    const int VT = 16;
    int tid = threadIdx.x, lane = tid & 31, warp = tid >> 5;
    if (tid == 0) s_carry = 0;
    __syncthreads();
    const int TILE = 1024 * VT;
    for (int base = 0; base < n; base += TILE) {
        int idx0 = base + tid * VT;
        int v[VT];
        int tsum = 0;
#pragma unroll
        for (int j = 0; j < VT; j++) {
            int i = idx0 + j;
            v[j] = (i < n) ? (g_deg[i] + 1) : 0;
            tsum += v[j];
        }
        int x = tsum;
#pragma unroll
        for (int o = 1; o < 32; o <<= 1) {
            int t = __shfl_up_sync(0xffffffffu, x, o);
            if (lane >= o) x += t;
        }
        if (lane == 31) warp_sums[warp] = x;
        __syncthreads();
        if (warp == 0) {
            int y = warp_sums[lane];
#pragma unroll
            for (int o = 1; o < 32; o <<= 1) {
                int t = __shfl_up_sync(0xffffffffu, y, o);
                if (lane >= o) y += t;
            }
            warp_sums[lane] = y;
        }
        __syncthreads();
        int warp_excl = (warp == 0) ? 0 : warp_sums[warp - 1];
        int run = s_carry + warp_excl + (x - tsum);
#pragma unroll
        for (int j = 0; j < VT; j++) {
            int i = idx0 + j;
            if (i < n) g_rowptr[i] = run;
            run += v[j];
        }
        __syncthreads();
        if (tid == 0) s_carry += warp_sums[31];
        __syncthreads();
    }
    if (tid == 0) g_rowptr[n] = s_carry;
}

__global__ void k_selfloop(int n) {
    int i = blockIdx.x * blockDim.x + threadIdx.x;
    if (i < n) {
        int p = g_rowptr[i];
        g_col[p] = i;
        g_cursor[i] = p + 1;
        g_dinv[i] = rsqrtf((float)(g_rowptr[i + 1] - p));
    }
}

__global__ void k_fill(const int* __restrict__ src, const int* __restrict__ dst, int e) {
    int i = blockIdx.x * blockDim.x + threadIdx.x;
    if (i < e) {
        int p = atomicAdd(&g_cursor[dst[i]], 1);
        g_col[p] = src[i];
    }
}

// ---------------- GCN (rank-1 collapse) ----------------
__global__ void k_gcn_agg(const float* __restrict__ sig, int n) {
    int i = blockIdx.x * blockDim.x + threadIdx.x;
    if (i >= n) return;
    int beg = g_rowptr[i], end = g_rowptr[i + 1];
    float s = 0.f;
    for (int j = beg; j < end; j++) {
        int u = g_col[j];
        s += g_dinv[u] * sig[u];
    }
    g_sagg[i] = s * g_dinv[i];
}

__global__ void k_gcn_x(const float* __restrict__ w, const float* __restrict__ b, int n) {
    int f = threadIdx.x;
    float wf = w[f], bf = b[f];
    int base = blockIdx.x * 64;
    float s1 = 0.f, s2 = 0.f;
    for (int r = 0; r < 64; r++) {
        int nd = base + r;
        if (nd >= n) break;
        float v = fmaxf(fmaf(g_sagg[nd], wf, bf), 0.f);
        g_x[nd * FF + f] = v;
        s1 += v;
        s2 += v * v;
    }
    atomicAdd(&g_s1[f], s1);
    atomicAdd(&g_s2[f], s2);
}

// ---------------- tensor-core helpers ----------------
__device__ __forceinline__ void mma16816(float c[4], unsigned a0, unsigned a1,
                                         unsigned a2, unsigned a3,
                                         unsigned b0, unsigned b1) {
    asm volatile(
        "mma.sync.aligned.m16n8k16.row.col.f32.f16.f16.f32 "
        "{%0,%1,%2,%3}, {%4,%5,%6,%7}, {%8,%9}, {%0,%1,%2,%3};"
        : "+f"(c[0]), "+f"(c[1]), "+f"(c[2]), "+f"(c[3])
        : "r"(a0), "r"(a1), "r"(a2), "r"(a3), "r"(b0), "r"(b1));
}

__device__ __forceinline__ void ldsm4(unsigned& a0, unsigned& a1, unsigned& a2,
                                      unsigned& a3, unsigned addr) {
    asm volatile("ldmatrix.sync.aligned.m8n8.x4.shared.b16 {%0,%1,%2,%3}, [%4];"
                 : "=r"(a0), "=r"(a1), "=r"(a2), "=r"(a3)
                 : "r"(addr));
}

// pack W[k][n] (fp32, k-major) -> Wp[s][q][n] uint2 = {h(16s+2q,n),h(16s+2q+1,n),
//                                                      h(16s+8+2q,n),h(16s+8+2q+1,n)}
template <int NOUT>
__device__ __forceinline__ void load_w_packed(const float* __restrict__ W, __half* Wsh,
                                              int tid, int nthr) {
    const int WPITCH = NOUT + 4;  // uint2 pitch -> conflict-free B loads
    const float4* W4 = (const float4*)W;
    for (int e4 = tid; e4 < FF * NOUT / 4; e4 += nthr) {
        int k = e4 / (NOUT / 4);
        int n0 = (e4 % (NOUT / 4)) * 4;
        float4 v = W4[e4];
        int s = k >> 4, r = k & 15;
        int w = r >> 3, q = (r & 7) >> 1, hs = r & 1;
        int base = ((s * 4 + q) * WPITCH) * 4 + w * 2 + hs;
#pragma unroll
        for (int j = 0; j < 4; j++)
            Wsh[base + (n0 + j) * 4] = __float2half((&v.x)[j]);
    }
}

// ---------------- layer GEMM: h = x @ W, fused GN-apply + attention coefs -----
// block 256 thr = 8 warps; M-tile 128, N = 128. warp: 64 rows x 32 cols.
template <int GN>
__global__ void k_mm(const float* __restrict__ W,
                     const float* __restrict__ atts, const float* __restrict__ attd,
                     const float* __restrict__ gnw, const float* __restrict__ gnb,
                     const float* __restrict__ gns, int grp, int n) {
    extern __shared__ char smem[];
    __half* Xs = (__half*)smem;                       // 128 * XP halves = 34816 B
    __half* Wsh = (__half*)(smem + 128 * XP * 2);     // 32 * 132 uint2 = 33792 B
    float* sm_mul = (float*)(smem + 128 * XP * 2 + 33792);
    float* sm_add = sm_mul + FF;
    const uint2* Wp = (const uint2*)Wsh;

    int tid = threadIdx.x;
    int blockRow = blockIdx.x * 128;

    if (GN) {
        if (tid < FF) {
            float invn = 1.0f / (float)n;
            float mu = g_s1[grp * FF + tid] * invn;
            float m2 = g_s2[grp * FF + tid] * invn;
            float mum = gns[tid] * mu;
            float var = m2 - 2.f * mum * mu + mum * mum;
            float inv = rsqrtf(var + 1e-5f);
            float ml = gnw[tid] * inv;
            sm_mul[tid] = ml;
            sm_add[tid] = gnb[tid] - mum * ml;
        }
        __syncthreads();
    }

    load_w_packed<FF>(W, Wsh, tid, 256);

    // load X tile (normalize + write back if GN), convert to fp16
    for (int i = tid; i < 128 * 32; i += 256) {
        int row = i >> 5, c4 = i & 31;
        int node = blockRow + row;
        float4 v = make_float4(0.f, 0.f, 0.f, 0.f);
        if (node < n) {
            v = ((const float4*)(g_x + (size_t)node * FF))[c4];
            if (GN) {
                int f = c4 * 4;
                v.x = v.x * sm_mul[f + 0] + sm_add[f + 0];
                v.y = v.y * sm_mul[f + 1] + sm_add[f + 1];
                v.z = v.z * sm_mul[f + 2] + sm_add[f + 2];
                v.w = v.w * sm_mul[f + 3] + sm_add[f + 3];
                ((float4*)(g_x + (size_t)node * FF))[c4] = v;
            }
        }
        __half2 p0 = __floats2half2_rn(v.x, v.y);
        __half2 p1 = __floats2half2_rn(v.z, v.w);
        uint2 pk;
        pk.x = *(unsigned*)&p0;
        pk.y = *(unsigned*)&p1;
        *(uint2*)(Xs + row * XP + c4 * 4) = pk;
    }
    __syncthreads();

    int warp = tid >> 5, lane = tid & 31;
    int warp_m = warp >> 2, warp_n = warp & 3;
    int colbase = warp_n * 32;

    float c[4][4][4];
#pragma unroll
    for (int a = 0; a < 4; a++)
#pragma unroll
        for (int bq = 0; bq < 4; bq++)
#pragma unroll
            for (int d = 0; d < 4; d++) c[a][bq][d] = 0.f;

    unsigned xs_base = (unsigned)__cvta_generic_to_shared(Xs);
    int lrow_add = ((lane >> 3) & 1) * 8 + (lane & 7);
    int lcol_b = (lane >> 4) * 16;

#pragma unroll
    for (int s = 0; s < 8; s++) {
        unsigned a[4][4];
#pragma unroll
        for (int mi = 0; mi < 4; mi++) {
            unsigned addr = xs_base +
                (warp_m * 64 + mi * 16 + lrow_add) * (XP * 2) + s * 32 + lcol_b;
            ldsm4(a[mi][0], a[mi][1], a[mi][2], a[mi][3], addr);
        }
        uint2 bb[4];
#pragma unroll
        for (int ni = 0; ni < 4; ni++)
            bb[ni] = Wp[(s * 4 + (lane & 3)) * (FF + 4) + colbase + ni * 8 + (lane >> 2)];
#pragma unroll
        for (int mi = 0; mi < 4; mi++)
#pragma unroll
            for (int ni = 0; ni < 4; ni++)
                mma16816(c[mi][ni], a[mi][0], a[mi][1], a[mi][2], a[mi][3],
                         bb[ni].x, bb[ni].y);
    }

    // epilogue: store h (fp16) + attention coefficients
    float2 aS[4], aD[4];
#pragma unroll
    for (int ni = 0; ni < 4; ni++) {
        int c2 = (colbase >> 1) + ni * 4 + (lane & 3);
        aS[ni] = ((const float2*)atts)[c2];
        aD[ni] = ((const float2*)attd)[c2];
    }
    int hd0 = colbase >> 4;

#pragma unroll
    for (int mi = 0; mi < 4; mi++) {
        int grA = blockRow + warp_m * 64 + mi * 16 + (lane >> 2);
        int grB = grA + 8;
        int col0 = colbase + (lane & 3) * 2;
        // h stores
        if (grA < n) {
            __half* hp = g_hh + (size_t)grA * FF + col0;
#pragma unroll
            for (int ni = 0; ni < 4; ni++) {
                __half2 hv = __floats2half2_rn(c[mi][ni][0], c[mi][ni][1]);
                *(__half2*)(hp + ni * 8) = hv;
            }
        }
        if (grB < n) {
            __half* hp = g_hh + (size_t)grB * FF + col0;
#pragma unroll
            for (int ni = 0; ni < 4; ni++) {
                __half2 hv = __floats2half2_rn(c[mi][ni][2], c[mi][ni][3]);
                *(__half2*)(hp + ni * 8) = hv;
            }
        }
        // attention coefs: heads hd0 (ni 0,1), hd0+1 (ni 2,3)
        float sAL = c[mi][0][0] * aS[0].x + c[mi][0][1] * aS[0].y +
                    c[mi][1][0] * aS[1].x + c[mi][1][1] * aS[1].y;
        float sAR = c[mi][2][0] * aS[2].x + c[mi][2][1] * aS[2].y +
                    c[mi][3][0] * aS[3].x + c[mi][3][1] * aS[3].y;
        float sBL = c[mi][0][2] * aS[0].x + c[mi][0][3] * aS[0].y +
                    c[mi][1][2] * aS[1].x + c[mi][1][3] * aS[1].y;
        float sBR = c[mi][2][2] * aS[2].x + c[mi][2][3] * aS[2].y +
                    c[mi][3][2] * aS[3].x + c[mi][3][3] * aS[3].y;
        float dAL = c[mi][0][0] * aD[0].x + c[mi][0][1] * aD[0].y +
                    c[mi][1][0] * aD[1].x + c[mi][1][1] * aD[1].y;
        float dAR = c[mi][2][0] * aD[2].x + c[mi][2][1] * aD[2].y +
                    c[mi][3][0] * aD[3].x + c[mi][3][1] * aD[3].y;
        float dBL = c[mi][0][2] * aD[0].x + c[mi][0][3] * aD[0].y +
                    c[mi][1][2] * aD[1].x + c[mi][1][3] * aD[1].y;
        float dBR = c[mi][2][2] * aD[2].x + c[mi][2][3] * aD[2].y +
                    c[mi][3][2] * aD[3].x + c[mi][3][3] * aD[3].y;
#pragma unroll
        for (int o = 1; o < 4; o <<= 1) {
            sAL += __shfl_xor_sync(0xffffffffu, sAL, o);
            sAR += __shfl_xor_sync(0xffffffffu, sAR, o);
            sBL += __shfl_xor_sync(0xffffffffu, sBL, o);
            sBR += __shfl_xor_sync(0xffffffffu, sBR, o);
            dAL += __shfl_xor_sync(0xffffffffu, dAL, o);
            dAR += __shfl_xor_sync(0xffffffffu, dAR, o);
            dBL += __shfl_xor_sync(0xffffffffu, dBL, o);
            dBR += __shfl_xor_sync(0xffffffffu, dBR, o);
        }
        if ((lane & 3) == 0) {
            if (grA < n) {
                g_as[grA * HH + hd0] = sAL;
                g_as[grA * HH + hd0 + 1] = sAR;
                g_ad[grA * HH + hd0] = dAL;
                g_ad[grA * HH + hd0 + 1] = dAR;
            }
            if (grB < n) {
                g_as[grB * HH + hd0] = sBL;
                g_as[grB * HH + hd0 + 1] = sBR;
                g_ad[grB * HH + hd0] = dBL;
                g_ad[grB * HH + hd0 + 1] = dBR;
            }
        }
    }
}

// ---------------- output projection: out = x @ lin_w + lin_b (N=64) -----------
__global__ void k_lin(const float* __restrict__ W, const float* __restrict__ b,
                      float* __restrict__ out, int n) {
    extern __shared__ char smem[];
    __half* Xs = (__half*)smem;                    // 34816 B
    __half* Wsh = (__half*)(smem + 128 * XP * 2);  // 32*68 uint2 = 17408 B
    const uint2* Wp = (const uint2*)Wsh;
    int tid = threadIdx.x;
    int blockRow = blockIdx.x * 128;

    load_w_packed<64>(W, Wsh, tid, 256);

    for (int i = tid; i < 128 * 32; i += 256) {
        int row = i >> 5, c4 = i & 31;
        int node = blockRow + row;
        float4 v = make_float4(0.f, 0.f, 0.f, 0.f);
        if (node < n) v = ((const float4*)(g_x + (size_t)node * FF))[c4];
        __half2 p0 = __floats2half2_rn(v.x, v.y);
        __half2 p1 = __floats2half2_rn(v.z, v.w);
        uint2 pk;
        pk.x = *(unsigned*)&p0;
        pk.y = *(unsigned*)&p1;
        *(uint2*)(Xs + row * XP + c4 * 4) = pk;
    }
    __syncthreads();

    int warp = tid >> 5, lane = tid & 31;
    int warp_m = warp >> 1, warp_n = warp & 1;
    int colbase = warp_n * 32;

    float c[2][4][4];
#pragma unroll
    for (int a = 0; a < 2; a++)
#pragma unroll
        for (int bq = 0; bq < 4; bq++)
#pragma unroll
            for (int d = 0; d < 4; d++) c[a][bq][d] = 0.f;

    unsigned xs_base = (unsigned)__cvta_generic_to_shared(Xs);
    int lrow_add = ((lane >> 3) & 1) * 8 + (lane & 7);
    int lcol_b = (lane >> 4) * 16;

#pragma unroll
    for (int s = 0; s < 8; s++) {
        unsigned a[2][4];
#pragma unroll
        for (int mi = 0; mi < 2; mi++) {
            unsigned addr = xs_base +
                (warp_m * 32 + mi * 16 + lrow_add) * (XP * 2) + s * 32 + lcol_b;
            ldsm4(a[mi][0], a[mi][1], a[mi][2], a[mi][3], addr);
        }
        uint2 bb[4];
#pragma unroll
        for (int ni = 0; ni < 4; ni++)
            bb[ni] = Wp[(s * 4 + (lane & 3)) * (64 + 4) + colbase + ni * 8 + (lane >> 2)];
#pragma unroll
        for (int mi = 0; mi < 2; mi++)
#pragma unroll
            for (int ni = 0; ni < 4; ni++)
                mma16816(c[mi][ni], a[mi][0], a[mi][1], a[mi][2], a[mi][3],
                         bb[ni].x, bb[ni].y);
    }

#pragma unroll
    for (int mi = 0; mi < 2; mi++) {
        int grA = blockRow + warp_m * 32 + mi * 16 + (lane >> 2);
        int grB = grA + 8;
        int col0 = colbase + (lane & 3) * 2;
#pragma unroll
        for (int ni = 0; ni < 4; ni++) {
            float2 bv = ((const float2*)b)[(col0 + ni * 8) >> 1];
            if (grA < n) {
                float2 o = make_float2(c[mi][ni][0] + bv.x, c[mi][ni][1] + bv.y);
                *(float2*)(out + (size_t)grA * 64 + col0 + ni * 8) = o;
            }
            if (grB < n) {
                float2 o = make_float2(c[mi][ni][2] + bv.x, c[mi][ni][3] + bv.y);
                *(float2*)(out + (size_t)grB * 64 + col0 + ni * 8) = o;
            }
        }
    }
}

// ---------------- edge softmax + aggregation + residual (warp per node) -------
template <int STATS>
__global__ void k_attn(const float* __restrict__ gb, int n) {
    __shared__ float bsum[FF];
    __shared__ float bsq[FF];
    int tid = threadIdx.x;
    int warp = tid >> 5, lane = tid & 31;
    int node = blockIdx.x * 8 + warp;

    if (STATS) {
        if (tid < FF) { bsum[tid] = 0.f; bsq[tid] = 0.f; }
        __syncthreads();
    }

    float4 xv = {0, 0, 0, 0};
    if (node < n) {
        int beg = g_rowptr[node], end = g_rowptr[node + 1];
        int hd = lane >> 2;
        float adh = g_ad[node * HH + hd];

        float s = 0.f;
        float4 acc = {0.f, 0.f, 0.f, 0.f};
        int j = beg;
        for (; j + 1 < end; j += 2) {
            int u0 = g_col[j], u1 = g_col[j + 1];
            float e0 = g_as[u0 * HH + hd] + adh;
            float e1 = g_as[u1 * HH + hd] + adh;
            e0 = e0 > 0.f ? e0 : 0.2f * e0;
            e1 = e1 > 0.f ? e1 : 0.2f * e1;
            float w0 = __expf(e0), w1 = __expf(e1);
            uint2 p0 = *(const uint2*)(g_hh + (size_t)u0 * FF + lane * 4);
            uint2 p1 = *(const uint2*)(g_hh + (size_t)u1 * FF + lane * 4);
            float2 h0a = __half22float2(*(__half2*)&p0.x);
            float2 h0b = __half22float2(*(__half2*)&p0.y);
            float2 h1a = __half22float2(*(__half2*)&p1.x);
            float2 h1b = __half22float2(*(__half2*)&p1.y);
            s += w0 + w1;
            acc.x += w0 * h0a.x + w1 * h1a.x;
            acc.y += w0 * h0a.y + w1 * h1a.y;
            acc.z += w0 * h0b.x + w1 * h1b.x;
            acc.w += w0 * h0b.y + w1 * h1b.y;
        }
        if (j < end) {
            int u0 = g_col[j];
            float e0 = g_as[u0 * HH + hd] + adh;
            e0 = e0 > 0.f ? e0 : 0.2f * e0;
            float w0 = __expf(e0);
            uint2 p0 = *(const uint2*)(g_hh + (size_t)u0 * FF + lane * 4);
            float2 h0a = __half22float2(*(__half2*)&p0.x);
            float2 h0b = __half22float2(*(__half2*)&p0.y);
            s += w0;
            acc.x += w0 * h0a.x;
            acc.y += w0 * h0a.y;
            acc.z += w0 * h0b.x;
            acc.w += w0 * h0b.y;
        }
        float rd = 1.0f / s;

        float4 b4 = ((const float4*)gb)[lane];
        xv = ((float4*)(g_x + (size_t)node * FF))[lane];
        xv.x += fmaxf(acc.x * rd + b4.x, 0.f);
        xv.y += fmaxf(acc.y * rd + b4.y, 0.f);
        xv.z += fmaxf(acc.z * rd + b4.z, 0.f);
        xv.w += fmaxf(acc.w * rd + b4.w, 0.f);
        ((float4*)(g_x + (size_t)node * FF))[lane] = xv;
    }

    if (STATS) {
        if (node < n) {
            int f0 = lane * 4;
            atomicAdd(&bsum[f0 + 0], xv.x); atomicAdd(&bsq[f0 + 0], xv.x * xv.x);
            atomicAdd(&bsum[f0 + 1], xv.y); atomicAdd(&bsq[f0 + 1], xv.y * xv.y);
            atomicAdd(&bsum[f0 + 2], xv.z); atomicAdd(&bsq[f0 + 2], xv.z * xv.z);
            atomicAdd(&bsum[f0 + 3], xv.w); atomicAdd(&bsq[f0 + 3], xv.w * xv.w);
        }
        __syncthreads();
        if (tid < FF) {
            atomicAdd(&g_s1[FF + tid], bsum[tid]);
            atomicAdd(&g_s2[FF + tid], bsq[tid]);
        }
    }
}

// ---------------- launch ----------------
extern "C" void kernel_launch(void* const* d_in, const int* in_sizes, int n_in,
                              void* d_out, int out_size) {
    const float* signals = (const float*)d_in[0];
    const int*   ei      = (const int*)d_in[1];
    const float* gcn_w   = (const float*)d_in[2];
    const float* gcn_b   = (const float*)d_in[3];
    const float* gat_w   = (const float*)d_in[4];
    const float* att_src = (const float*)d_in[5];
    const float* att_dst = (const float*)d_in[6];
    const float* gat_b   = (const float*)d_in[7];
    const float* gn_w    = (const float*)d_in[8];
    const float* gn_b    = (const float*)d_in[9];
    const float* gn_s    = (const float*)d_in[10];
    const float* lin_w   = (const float*)d_in[11];
    const float* lin_b   = (const float*)d_in[12];

    int n = in_sizes[0];
    int e = in_sizes[1] / 2;
    const int* src = ei;
    const int* dst = ei + e;

    const int MM_SMEM = 128 * XP * 2 + 33792 + 2 * FF * 4;  // 69632
    const int LIN_SMEM = 128 * XP * 2 + 17408;              // 52224
    cudaFuncSetAttribute(k_mm<0>, cudaFuncAttributeMaxDynamicSharedMemorySize, MM_SMEM);
    cudaFuncSetAttribute(k_mm<1>, cudaFuncAttributeMaxDynamicSharedMemorySize, MM_SMEM);
    cudaFuncSetAttribute(k_lin, cudaFuncAttributeMaxDynamicSharedMemorySize, LIN_SMEM);

    const int B = 256;
    k_zero<<<(n + B - 1) / B, B>>>(n);
    k_deg_edges<<<(e + B - 1) / B, B>>>(dst, e);
    k_scan<<<1, 1024>>>(n);
    k_selfloop<<<(n + B - 1) / B, B>>>(n);
    k_fill<<<(e + B - 1) / B, B>>>(src, dst, e);

    k_gcn_agg<<<(n + B - 1) / B, B>>>(signals, n);
    k_gcn_x<<<(n + 63) / 64, 128>>>(gcn_w, gcn_b, n);  // + GN group-0 stats

    int grid_mm = (n + 127) / 128;
    for (int i = 0; i < NLAY; i++) {
        const float* Wl = gat_w + (size_t)i * FF * FF;
        const float* aS = att_src + i * HH * CC;
        const float* aD = att_dst + i * HH * CC;
        if (i % GNFREQ == 0) {
            int g = i / GNFREQ;
            k_mm<1><<<grid_mm, 256, MM_SMEM>>>(Wl, aS, aD, gn_w + g * FF,
                                               gn_b + g * FF, gn_s + g * FF, g, n);
        } else {
            k_mm<0><<<grid_mm, 256, MM_SMEM>>>(Wl, aS, aD, nullptr, nullptr, nullptr, 0, n);
        }
        if (i == 2) {
            k_attn<1><<<(n + 7) / 8, 256>>>(gat_b + i * FF, n);  // + GN group-1 stats
        } else {
            k_attn<0><<<(n + 7) / 8, 256>>>(gat_b + i * FF, n);
        }
    }

    k_lin<<<grid_mm, 256, LIN_SMEM>>>(lin_w, lin_b, (float*)d_out, n);
}

// round 5
// speedup vs baseline: 2.1043x; 1.0041x over previous
#include <cuda_runtime.h>
#include <cuda_fp16.h>
#include <cstdint>
#include <cstddef>
#include <math.h>

#define NN 50000
#define EE 800000
#define FF 128
#define HH 8
#define CC 16
#define NLAY 5
#define GNFREQ 3
#define ETOT (EE + NN)

// Xs row pitch in halves (272 B): 68 words %32 = 4 banks/row -> conflict-free ldmatrix
#define XP 136

// ---------------- device scratch ----------------
__device__ float  g_x[NN * FF];
__device__ __half g_hh[NN * FF];
__device__ float  g_as[NN * HH];
__device__ float  g_ad[NN * HH];
__device__ float  g_sagg[NN];
__device__ float  g_dinv[NN];
__device__ int    g_rowptr[NN + 1];
__device__ int    g_deg[NN];
__device__ int    g_cursor[NN];
__device__ int    g_col[ETOT];
__device__ float  g_s1[2 * FF];
__device__ float  g_s2[2 * FF];

// ---------------- CSR build ----------------
__global__ void k_zero(int n) {
    int i = blockIdx.x * blockDim.x + threadIdx.x;
    if (i < n) g_deg[i] = 0;
    if (i < 2 * FF) { g_s1[i] = 0.f; g_s2[i] = 0.f; }
}

__global__ void k_deg_edges(const int* __restrict__ dst, int e) {
    int i = blockIdx.x * blockDim.x + threadIdx.x;
    if (i < e) atomicAdd(&g_deg[dst[i]], 1);
}

__global__ void k_scan(int n) {
    __shared__ int warp_sums[32];
    __shared__ int s_carry;
    const int VT = 16;
    int tid = threadIdx.x, lane = tid & 31, warp = tid >> 5;
    if (tid == 0) s_carry = 0;
    __syncthreads();
    const int TILE = 1024 * VT;
    for (int base = 0; base < n; base += TILE) {
        int idx0 = base + tid * VT;
        int v[VT];
        int tsum = 0;
#pragma unroll
        for (int j = 0; j < VT; j++) {
            int i = idx0 + j;
            v[j] = (i < n) ? (g_deg[i] + 1) : 0;
            tsum += v[j];
        }
        int x = tsum;
#pragma unroll
        for (int o = 1; o < 32; o <<= 1) {
            int t = __shfl_up_sync(0xffffffffu, x, o);
            if (lane >= o) x += t;
        }
        if (lane == 31) warp_sums[warp] = x;
        __syncthreads();
        if (warp == 0) {
            int y = warp_sums[lane];
#pragma unroll
            for (int o = 1; o < 32; o <<= 1) {
                int t = __shfl_up_sync(0xffffffffu, y, o);
                if (lane >= o) y += t;
            }
            warp_sums[lane] = y;
        }
        __syncthreads();
        int warp_excl = (warp == 0) ? 0 : warp_sums[warp - 1];
        int run = s_carry + warp_excl + (x - tsum);
#pragma unroll
        for (int j = 0; j < VT; j++) {
            int i = idx0 + j;
            if (i < n) g_rowptr[i] = run;
            run += v[j];
        }
        __syncthreads();
        if (tid == 0) s_carry += warp_sums[31];
        __syncthreads();
    }
    if (tid == 0) g_rowptr[n] = s_carry;
}

__global__ void k_selfloop(int n) {
    int i = blockIdx.x * blockDim.x + threadIdx.x;
    if (i < n) {
        int p = g_rowptr[i];
        g_col[p] = i;
        g_cursor[i] = p + 1;
        g_dinv[i] = rsqrtf((float)(g_rowptr[i + 1] - p));
    }
}

__global__ void k_fill(const int* __restrict__ src, const int* __restrict__ dst, int e) {
    int i = blockIdx.x * blockDim.x + threadIdx.x;
    if (i < e) {
        int p = atomicAdd(&g_cursor[dst[i]], 1);
        g_col[p] = src[i];
    }
}

// ---------------- GCN (rank-1 collapse) ----------------
__global__ void k_gcn_agg(const float* __restrict__ sig, int n) {
    int i = blockIdx.x * blockDim.x + threadIdx.x;
    if (i >= n) return;
    int beg = g_rowptr[i], end = g_rowptr[i + 1];
    float s = 0.f;
    for (int j = beg; j < end; j++) {
        int u = g_col[j];
        s += g_dinv[u] * sig[u];
    }
    g_sagg[i] = s * g_dinv[i];
}

__global__ void k_gcn_x(const float* __restrict__ w, const float* __restrict__ b, int n) {
    int f = threadIdx.x;
    float wf = w[f], bf = b[f];
    int base = blockIdx.x * 64;
    float s1 = 0.f, s2 = 0.f;
    for (int r = 0; r < 64; r++) {
        int nd = base + r;
        if (nd >= n) break;
        float v = fmaxf(fmaf(g_sagg[nd], wf, bf), 0.f);
        g_x[nd * FF + f] = v;
        s1 += v;
        s2 += v * v;
    }
    atomicAdd(&g_s1[f], s1);
    atomicAdd(&g_s2[f], s2);
}

// ---------------- tensor-core helpers ----------------
__device__ __forceinline__ void mma16816(float c[4], unsigned a0, unsigned a1,
                                         unsigned a2, unsigned a3,
                                         unsigned b0, unsigned b1) {
    asm volatile(
        "mma.sync.aligned.m16n8k16.row.col.f32.f16.f16.f32 "
        "{%0,%1,%2,%3}, {%4,%5,%6,%7}, {%8,%9}, {%0,%1,%2,%3};"
        : "+f"(c[0]), "+f"(c[1]), "+f"(c[2]), "+f"(c[3])
        : "r"(a0), "r"(a1), "r"(a2), "r"(a3), "r"(b0), "r"(b1));
}

__device__ __forceinline__ void ldsm4(unsigned& a0, unsigned& a1, unsigned& a2,
                                      unsigned& a3, unsigned addr) {
    asm volatile("ldmatrix.sync.aligned.m8n8.x4.shared.b16 {%0,%1,%2,%3}, [%4];"
                 : "=r"(a0), "=r"(a1), "=r"(a2), "=r"(a3)
                 : "r"(addr));
}

// pack W[k][n] (fp32, k-major) -> fragment-order halves in shared
template <int NOUT>
__device__ __forceinline__ void load_w_packed(const float* __restrict__ W, __half* Wsh,
                                              int tid, int nthr) {
    const int WPITCH = NOUT + 4;  // uint2 pitch -> conflict-free B loads
    const float4* W4 = (const float4*)W;
    for (int e4 = tid; e4 < FF * NOUT / 4; e4 += nthr) {
        int k = e4 / (NOUT / 4);
        int n0 = (e4 % (NOUT / 4)) * 4;
        float4 v = W4[e4];
        int s = k >> 4, r = k & 15;
        int w = r >> 3, q = (r & 7) >> 1, hs = r & 1;
        int base = ((s * 4 + q) * WPITCH) * 4 + w * 2 + hs;
#pragma unroll
        for (int j = 0; j < 4; j++)
            Wsh[base + (n0 + j) * 4] = __float2half((&v.x)[j]);
    }
}

// ---------------- layer GEMM: h = x @ W, fused GN-apply + attention coefs -----
template <int GN>
__global__ void k_mm(const float* __restrict__ W,
                     const float* __restrict__ atts, const float* __restrict__ attd,
                     const float* __restrict__ gnw, const float* __restrict__ gnb,
                     const float* __restrict__ gns, int grp, int n) {
    extern __shared__ char smem[];
    __half* Xs = (__half*)smem;                       // 128 * XP halves = 34816 B
    __half* Wsh = (__half*)(smem + 128 * XP * 2);     // 32 * 132 uint2 = 33792 B
    float* sm_mul = (float*)(smem + 128 * XP * 2 + 33792);
    float* sm_add = sm_mul + FF;
    const uint2* Wp = (const uint2*)Wsh;

    int tid = threadIdx.x;
    int blockRow = blockIdx.x * 128;

    if (GN) {
        if (tid < FF) {
            float invn = 1.0f / (float)n;
            float mu = g_s1[grp * FF + tid] * invn;
            float m2 = g_s2[grp * FF + tid] * invn;
            float mum = gns[tid] * mu;
            float var = m2 - 2.f * mum * mu + mum * mum;
            float inv = rsqrtf(var + 1e-5f);
            float ml = gnw[tid] * inv;
            sm_mul[tid] = ml;
            sm_add[tid] = gnb[tid] - mum * ml;
        }
        __syncthreads();
    }

    load_w_packed<FF>(W, Wsh, tid, 256);

    for (int i = tid; i < 128 * 32; i += 256) {
        int row = i >> 5, c4 = i & 31;
        int node = blockRow + row;
        float4 v = make_float4(0.f, 0.f, 0.f, 0.f);
        if (node < n) {
            v = ((const float4*)(g_x + (size_t)node * FF))[c4];
            if (GN) {
                int f = c4 * 4;
                v.x = v.x * sm_mul[f + 0] + sm_add[f + 0];
                v.y = v.y * sm_mul[f + 1] + sm_add[f + 1];
                v.z = v.z * sm_mul[f + 2] + sm_add[f + 2];
                v.w = v.w * sm_mul[f + 3] + sm_add[f + 3];
                ((float4*)(g_x + (size_t)node * FF))[c4] = v;
            }
        }
        __half2 p0 = __floats2half2_rn(v.x, v.y);
        __half2 p1 = __floats2half2_rn(v.z, v.w);
        uint2 pk;
        pk.x = *(unsigned*)&p0;
        pk.y = *(unsigned*)&p1;
        *(uint2*)(Xs + row * XP + c4 * 4) = pk;
    }
    __syncthreads();

    int warp = tid >> 5, lane = tid & 31;
    int warp_m = warp >> 2, warp_n = warp & 3;
    int colbase = warp_n * 32;

    float c[4][4][4];
#pragma unroll
    for (int a = 0; a < 4; a++)
#pragma unroll
        for (int bq = 0; bq < 4; bq++)
#pragma unroll
            for (int d = 0; d < 4; d++) c[a][bq][d] = 0.f;

    unsigned xs_base = (unsigned)__cvta_generic_to_shared(Xs);
    int lrow_add = ((lane >> 3) & 1) * 8 + (lane & 7);
    int lcol_b = (lane >> 4) * 16;

#pragma unroll
    for (int s = 0; s < 8; s++) {
        unsigned a[4][4];
#pragma unroll
        for (int mi = 0; mi < 4; mi++) {
            unsigned addr = xs_base +
                (warp_m * 64 + mi * 16 + lrow_add) * (XP * 2) + s * 32 + lcol_b;
            ldsm4(a[mi][0], a[mi][1], a[mi][2], a[mi][3], addr);
        }
        uint2 bb[4];
#pragma unroll
        for (int ni = 0; ni < 4; ni++)
            bb[ni] = Wp[(s * 4 + (lane & 3)) * (FF + 4) + colbase + ni * 8 + (lane >> 2)];
#pragma unroll
        for (int mi = 0; mi < 4; mi++)
#pragma unroll
            for (int ni = 0; ni < 4; ni++)
                mma16816(c[mi][ni], a[mi][0], a[mi][1], a[mi][2], a[mi][3],
                         bb[ni].x, bb[ni].y);
    }

    float2 aS[4], aD[4];
#pragma unroll
    for (int ni = 0; ni < 4; ni++) {
        int c2 = (colbase >> 1) + ni * 4 + (lane & 3);
        aS[ni] = ((const float2*)atts)[c2];
        aD[ni] = ((const float2*)attd)[c2];
    }
    int hd0 = colbase >> 4;

#pragma unroll
    for (int mi = 0; mi < 4; mi++) {
        int grA = blockRow + warp_m * 64 + mi * 16 + (lane >> 2);
        int grB = grA + 8;
        int col0 = colbase + (lane & 3) * 2;
        if (grA < n) {
            __half* hp = g_hh + (size_t)grA * FF + col0;
#pragma unroll
            for (int ni = 0; ni < 4; ni++) {
                __half2 hv = __floats2half2_rn(c[mi][ni][0], c[mi][ni][1]);
                *(__half2*)(hp + ni * 8) = hv;
            }
        }
        if (grB < n) {
            __half* hp = g_hh + (size_t)grB * FF + col0;
#pragma unroll
            for (int ni = 0; ni < 4; ni++) {
                __half2 hv = __floats2half2_rn(c[mi][ni][2], c[mi][ni][3]);
                *(__half2*)(hp + ni * 8) = hv;
            }
        }
        float sAL = c[mi][0][0] * aS[0].x + c[mi][0][1] * aS[0].y +
                    c[mi][1][0] * aS[1].x + c[mi][1][1] * aS[1].y;
        float sAR = c[mi][2][0] * aS[2].x + c[mi][2][1] * aS[2].y +
                    c[mi][3][0] * aS[3].x + c[mi][3][1] * aS[3].y;
        float sBL = c[mi][0][2] * aS[0].x + c[mi][0][3] * aS[0].y +
                    c[mi][1][2] * aS[1].x + c[mi][1][3] * aS[1].y;
        float sBR = c[mi][2][2] * aS[2].x + c[mi][2][3] * aS[2].y +
                    c[mi][3][2] * aS[3].x + c[mi][3][3] * aS[3].y;
        float dAL = c[mi][0][0] * aD[0].x + c[mi][0][1] * aD[0].y +
                    c[mi][1][0] * aD[1].x + c[mi][1][1] * aD[1].y;
        float dAR = c[mi][2][0] * aD[2].x + c[mi][2][1] * aD[2].y +
                    c[mi][3][0] * aD[3].x + c[mi][3][1] * aD[3].y;
        float dBL = c[mi][0][2] * aD[0].x + c[mi][0][3] * aD[0].y +
                    c[mi][1][2] * aD[1].x + c[mi][1][3] * aD[1].y;
        float dBR = c[mi][2][2] * aD[2].x + c[mi][2][3] * aD[2].y +
                    c[mi][3][2] * aD[3].x + c[mi][3][3] * aD[3].y;
#pragma unroll
        for (int o = 1; o < 4; o <<= 1) {
            sAL += __shfl_xor_sync(0xffffffffu, sAL, o);
            sAR += __shfl_xor_sync(0xffffffffu, sAR, o);
            sBL += __shfl_xor_sync(0xffffffffu, sBL, o);
            sBR += __shfl_xor_sync(0xffffffffu, sBR, o);
            dAL += __shfl_xor_sync(0xffffffffu, dAL, o);
            dAR += __shfl_xor_sync(0xffffffffu, dAR, o);
            dBL += __shfl_xor_sync(0xffffffffu, dBL, o);
            dBR += __shfl_xor_sync(0xffffffffu, dBR, o);
        }
        if ((lane & 3) == 0) {
            if (grA < n) {
                g_as[grA * HH + hd0] = sAL;
                g_as[grA * HH + hd0 + 1] = sAR;
                g_ad[grA * HH + hd0] = dAL;
                g_ad[grA * HH + hd0 + 1] = dAR;
            }
            if (grB < n) {
                g_as[grB * HH + hd0] = sBL;
                g_as[grB * HH + hd0 + 1] = sBR;
                g_ad[grB * HH + hd0] = dBL;
                g_ad[grB * HH + hd0 + 1] = dBR;
            }
        }
    }
}

// ---------------- output projection: out = x @ lin_w + lin_b (N=64) -----------
__global__ void k_lin(const float* __restrict__ W, const float* __restrict__ b,
                      float* __restrict__ out, int n) {
    extern __shared__ char smem[];
    __half* Xs = (__half*)smem;                    // 34816 B
    __half* Wsh = (__half*)(smem + 128 * XP * 2);  // 32*68 uint2 = 17408 B
    const uint2* Wp = (const uint2*)Wsh;
    int tid = threadIdx.x;
    int blockRow = blockIdx.x * 128;

    load_w_packed<64>(W, Wsh, tid, 256);

    for (int i = tid; i < 128 * 32; i += 256) {
        int row = i >> 5, c4 = i & 31;
        int node = blockRow + row;
        float4 v = make_float4(0.f, 0.f, 0.f, 0.f);
        if (node < n) v = ((const float4*)(g_x + (size_t)node * FF))[c4];
        __half2 p0 = __floats2half2_rn(v.x, v.y);
        __half2 p1 = __floats2half2_rn(v.z, v.w);
        uint2 pk;
        pk.x = *(unsigned*)&p0;
        pk.y = *(unsigned*)&p1;
        *(uint2*)(Xs + row * XP + c4 * 4) = pk;
    }
    __syncthreads();

    int warp = tid >> 5, lane = tid & 31;
    int warp_m = warp >> 1, warp_n = warp & 1;
    int colbase = warp_n * 32;

    float c[2][4][4];
#pragma unroll
    for (int a = 0; a < 2; a++)
#pragma unroll
        for (int bq = 0; bq < 4; bq++)
#pragma unroll
            for (int d = 0; d < 4; d++) c[a][bq][d] = 0.f;

    unsigned xs_base = (unsigned)__cvta_generic_to_shared(Xs);
    int lrow_add = ((lane >> 3) & 1) * 8 + (lane & 7);
    int lcol_b = (lane >> 4) * 16;

#pragma unroll
    for (int s = 0; s < 8; s++) {
        unsigned a[2][4];
#pragma unroll
        for (int mi = 0; mi < 2; mi++) {
            unsigned addr = xs_base +
                (warp_m * 32 + mi * 16 + lrow_add) * (XP * 2) + s * 32 + lcol_b;
            ldsm4(a[mi][0], a[mi][1], a[mi][2], a[mi][3], addr);
        }
        uint2 bb[4];
#pragma unroll
        for (int ni = 0; ni < 4; ni++)
            bb[ni] = Wp[(s * 4 + (lane & 3)) * (64 + 4) + colbase + ni * 8 + (lane >> 2)];
#pragma unroll
        for (int mi = 0; mi < 2; mi++)
#pragma unroll
            for (int ni = 0; ni < 4; ni++)
                mma16816(c[mi][ni], a[mi][0], a[mi][1], a[mi][2], a[mi][3],
                         bb[ni].x, bb[ni].y);
    }

#pragma unroll
    for (int mi = 0; mi < 2; mi++) {
        int grA = blockRow + warp_m * 32 + mi * 16 + (lane >> 2);
        int grB = grA + 8;
        int col0 = colbase + (lane & 3) * 2;
#pragma unroll
        for (int ni = 0; ni < 4; ni++) {
            float2 bv = ((const float2*)b)[(col0 + ni * 8) >> 1];
            if (grA < n) {
                float2 o = make_float2(c[mi][ni][0] + bv.x, c[mi][ni][1] + bv.y);
                *(float2*)(out + (size_t)grA * 64 + col0 + ni * 8) = o;
            }
            if (grB < n) {
                float2 o = make_float2(c[mi][ni][2] + bv.x, c[mi][ni][3] + bv.y);
                *(float2*)(out + (size_t)grB * 64 + col0 + ni * 8) = o;
            }
        }
    }
}

// ---------------- edge softmax + aggregation + residual ----------------------
// Warp per node; TWO edges in flight per warp instruction:
//   half = lane>>4 selects the edge, fl = lane&15 selects 8 features (one
//   LDG.128 of fp16 per lane). Cross-half reduction (9 shuffles) at the end.
template <int STATS>
__global__ void k_attn(const float* __restrict__ gb, int n) {
    __shared__ float bsum[FF];
    __shared__ float bsq[FF];
    int tid = threadIdx.x;
    int warp = tid >> 5, lane = tid & 31;
    int node = blockIdx.x * 8 + warp;

    if (STATS) {
        if (tid < FF) { bsum[tid] = 0.f; bsq[tid] = 0.f; }
        __syncthreads();
    }

    int half = lane >> 4, fl = lane & 15;
    int hd = fl >> 1;           // head of features fl*8..fl*8+7
    int f0 = fl * 8 + half * 4; // the float4 this lane finally owns

    float4 xv = {0, 0, 0, 0};
    if (node < n) {
        int beg = g_rowptr[node], end = g_rowptr[node + 1];
        float adh = g_ad[node * HH + hd];

        float s = 0.f;
        float acc[8] = {0.f, 0.f, 0.f, 0.f, 0.f, 0.f, 0.f, 0.f};

#pragma unroll 2
        for (int jb = beg; jb < end; jb += 2) {
            int j = jb + half;
            bool valid = (j < end);
            int u = valid ? g_col[j] : node;
            float ev = g_as[u * HH + hd] + adh;
            ev = ev > 0.f ? ev : 0.2f * ev;
            float w = valid ? __expf(ev) : 0.f;
            float4 hv4 = *(const float4*)(g_hh + (size_t)u * FF + fl * 8);
            const __half2* hp = (const __half2*)&hv4;
            s += w;
#pragma unroll
            for (int q = 0; q < 4; q++) {
                float2 f = __half22float2(hp[q]);
                acc[2 * q + 0] += w * f.x;
                acc[2 * q + 1] += w * f.y;
            }
        }

        // combine the two half-warp edge streams
        s += __shfl_xor_sync(0xffffffffu, s, 16);
#pragma unroll
        for (int q = 0; q < 8; q++)
            acc[q] += __shfl_xor_sync(0xffffffffu, acc[q], 16);
        float rd = 1.0f / s;

        float4 b4 = *(const float4*)(gb + f0);
        float* xp = g_x + (size_t)node * FF + f0;
        xv = *(float4*)xp;
        int o = half * 4;
        xv.x += fmaxf(acc[o + 0] * rd + b4.x, 0.f);
        xv.y += fmaxf(acc[o + 1] * rd + b4.y, 0.f);
        xv.z += fmaxf(acc[o + 2] * rd + b4.z, 0.f);
        xv.w += fmaxf(acc[o + 3] * rd + b4.w, 0.f);
        *(float4*)xp = xv;
    }

    if (STATS) {
        if (node < n) {
            atomicAdd(&bsum[f0 + 0], xv.x); atomicAdd(&bsq[f0 + 0], xv.x * xv.x);
            atomicAdd(&bsum[f0 + 1], xv.y); atomicAdd(&bsq[f0 + 1], xv.y * xv.y);
            atomicAdd(&bsum[f0 + 2], xv.z); atomicAdd(&bsq[f0 + 2], xv.z * xv.z);
            atomicAdd(&bsum[f0 + 3], xv.w); atomicAdd(&bsq[f0 + 3], xv.w * xv.w);
        }
        __syncthreads();
        if (tid < FF) {
            atomicAdd(&g_s1[FF + tid], bsum[tid]);
            atomicAdd(&g_s2[FF + tid], bsq[tid]);
        }
    }
}

// ---------------- launch ----------------
extern "C" void kernel_launch(void* const* d_in, const int* in_sizes, int n_in,
                              void* d_out, int out_size) {
    const float* signals = (const float*)d_in[0];
    const int*   ei      = (const int*)d_in[1];
    const float* gcn_w   = (const float*)d_in[2];
    const float* gcn_b   = (const float*)d_in[3];
    const float* gat_w   = (const float*)d_in[4];
    const float* att_src = (const float*)d_in[5];
    const float* att_dst = (const float*)d_in[6];
    const float* gat_b   = (const float*)d_in[7];
    const float* gn_w    = (const float*)d_in[8];
    const float* gn_b    = (const float*)d_in[9];
    const float* gn_s    = (const float*)d_in[10];
    const float* lin_w   = (const float*)d_in[11];
    const float* lin_b   = (const float*)d_in[12];

    int n = in_sizes[0];
    int e = in_sizes[1] / 2;
    const int* src = ei;
    const int* dst = ei + e;

    const int MM_SMEM = 128 * XP * 2 + 33792 + 2 * FF * 4;  // 69632
    const int LIN_SMEM = 128 * XP * 2 + 17408;              // 52224
    cudaFuncSetAttribute(k_mm<0>, cudaFuncAttributeMaxDynamicSharedMemorySize, MM_SMEM);
    cudaFuncSetAttribute(k_mm<1>, cudaFuncAttributeMaxDynamicSharedMemorySize, MM_SMEM);
    cudaFuncSetAttribute(k_lin, cudaFuncAttributeMaxDynamicSharedMemorySize, LIN_SMEM);

    const int B = 256;
    k_zero<<<(n + B - 1) / B, B>>>(n);
    k_deg_edges<<<(e + B - 1) / B, B>>>(dst, e);
    k_scan<<<1, 1024>>>(n);
    k_selfloop<<<(n + B - 1) / B, B>>>(n);
    k_fill<<<(e + B - 1) / B, B>>>(src, dst, e);

    k_gcn_agg<<<(n + B - 1) / B, B>>>(signals, n);
    k_gcn_x<<<(n + 63) / 64, 128>>>(gcn_w, gcn_b, n);  // + GN group-0 stats

    int grid_mm = (n + 127) / 128;
    for (int i = 0; i < NLAY; i++) {
        const float* Wl = gat_w + (size_t)i * FF * FF;
        const float* aS = att_src + i * HH * CC;
        const float* aD = att_dst + i * HH * CC;
        if (i % GNFREQ == 0) {
            int g = i / GNFREQ;
            k_mm<1><<<grid_mm, 256, MM_SMEM>>>(Wl, aS, aD, gn_w + g * FF,
                                               gn_b + g * FF, gn_s + g * FF, g, n);
        } else {
            k_mm<0><<<grid_mm, 256, MM_SMEM>>>(Wl, aS, aD, nullptr, nullptr, nullptr, 0, n);
        }
        if (i == 2) {
            k_attn<1><<<(n + 7) / 8, 256>>>(gat_b + i * FF, n);  // + GN group-1 stats
        } else {
            k_attn<0><<<(n + 7) / 8, 256>>>(gat_b + i * FF, n);
        }
    }

    k_lin<<<grid_mm, 256, LIN_SMEM>>>(lin_w, lin_b, (float*)d_out, n);
}